// round 7
// baseline (speedup 1.0000x reference)
#include <cuda_runtime.h>

// ----------------------------------------------------------------------------
// MultiHeadAttention, fp32.
// Stage 1/3: 128x128x16 SGEMM, 8x8 micro-tile, cp.async double-buffered.
// Stage 2: flash attention Br=Bc=64 (R5-validated version, unchanged).
// ----------------------------------------------------------------------------

constexpr int BATCH = 2;
constexpr int SEQ   = 2048;
constexpr int DM    = 768;
constexpr int NH    = 12;
constexpr int HD    = 64;
constexpr int BH    = BATCH * NH;   // 24
constexpr int MTOT  = BATCH * SEQ;  // 4096
constexpr int NTILES = SEQ / 64;    // 32
constexpr int NKT   = DM / 16;      // 48 k-tiles
constexpr float NEGV  = -10000.0f;
constexpr float SCALE = 0.125f;

constexpr int AS_STRIDE = 20;       // floats per A row (16 + 4 pad, 16B aligned)

__device__ float g_Q[BATCH * NH * SEQ * HD];
__device__ float g_K[BATCH * NH * SEQ * HD];
__device__ float g_V[BATCH * NH * SEQ * HD];
__device__ float g_O[BATCH * NH * SEQ * HD];

__device__ __forceinline__ void cp_async16(void* smem_dst, const void* gmem_src) {
    unsigned saddr = (unsigned)__cvta_generic_to_shared(smem_dst);
    asm volatile("cp.async.ca.shared.global [%0], [%1], 16;\n" :: "r"(saddr), "l"(gmem_src));
}
__device__ __forceinline__ void cp_commit() {
    asm volatile("cp.async.commit_group;\n");
}
template <int N>
__device__ __forceinline__ void cp_wait() {
    asm volatile("cp.async.wait_group %0;\n" :: "n"(N));
}

__device__ __forceinline__ float f4_get(const float4& v, int j) {
    return j == 0 ? v.x : j == 1 ? v.y : j == 2 ? v.z : v.w;
}

// ----------------------------------------------------------------------------
// Shared SGEMM body: C[128,128] tile, K=768, A row-major [m][k], B [k][n].
// acc produced in registers; caller does the epilogue.
// ----------------------------------------------------------------------------
struct GemmSmem {
    float As[2][128 * AS_STRIDE];
    float Bs[2][16 * 128];
};

__device__ __forceinline__ void gemm_mainloop(
    GemmSmem* s, const float* __restrict__ Arow0, size_t Astride,
    const float* __restrict__ B, int n0, float acc[8][8],
    int tid)
{
    const int tx = tid & 15, ty = tid >> 4;
    const int am = tid >> 1;
    const int ak = (tid & 1) * 8;
    const int kb = tid >> 5;
    const int nb = (tid & 31) * 4;

    const float* aptr = Arow0 + (size_t)am * Astride + ak;

    // prologue: issue tile 0 into buffer 0
    cp_async16(&s->As[0][am * AS_STRIDE + ak],     aptr);
    cp_async16(&s->As[0][am * AS_STRIDE + ak + 4], aptr + 4);
    cp_async16(&s->Bs[0][kb * 128 + nb],       &B[(size_t)kb * DM + n0 + nb]);
    cp_async16(&s->Bs[0][(kb + 8) * 128 + nb], &B[(size_t)(kb + 8) * DM + n0 + nb]);
    cp_commit();

    int buf = 0;
    for (int t = 0; t < NKT; ++t) {
        int k0n = (t + 1) * 16;
        if (t + 1 < NKT) {
            int nb2 = buf ^ 1;
            cp_async16(&s->As[nb2][am * AS_STRIDE + ak],     aptr + k0n);
            cp_async16(&s->As[nb2][am * AS_STRIDE + ak + 4], aptr + k0n + 4);
            cp_async16(&s->Bs[nb2][kb * 128 + nb],       &B[(size_t)(k0n + kb) * DM + n0 + nb]);
            cp_async16(&s->Bs[nb2][(kb + 8) * 128 + nb], &B[(size_t)(k0n + kb + 8) * DM + n0 + nb]);
            cp_commit();
            cp_wait<1>();
        } else {
            cp_wait<0>();
        }
        __syncthreads();

        const float* As = s->As[buf];
        const float* Bs = s->Bs[buf];
        #pragma unroll
        for (int kk = 0; kk < 16; kk += 4) {
            float4 a[8];
            #pragma unroll
            for (int i = 0; i < 8; ++i)
                a[i] = *reinterpret_cast<const float4*>(&As[(ty * 8 + i) * AS_STRIDE + kk]);
            #pragma unroll
            for (int j = 0; j < 4; ++j) {
                float4 rb0 = *reinterpret_cast<const float4*>(&Bs[(kk + j) * 128 + tx * 8]);
                float4 rb1 = *reinterpret_cast<const float4*>(&Bs[(kk + j) * 128 + tx * 8 + 4]);
                float br[8] = {rb0.x, rb0.y, rb0.z, rb0.w, rb1.x, rb1.y, rb1.z, rb1.w};
                #pragma unroll
                for (int i = 0; i < 8; ++i) {
                    float av = f4_get(a[i], j);
                    #pragma unroll
                    for (int c = 0; c < 8; ++c)
                        acc[i][c] += av * br[c];
                }
            }
        }
        buf ^= 1;
        __syncthreads();
    }
}

// ----------------------------------------------------------------------------
// Stage 1: QKV projections. grid = (DM/128, MTOT/128, 3), 256 threads.
// ----------------------------------------------------------------------------
__global__ void __launch_bounds__(256) qkv_proj_kernel(
    const float* __restrict__ q, const float* __restrict__ k, const float* __restrict__ v,
    const float* __restrict__ Wq, const float* __restrict__ Wk, const float* __restrict__ Wv)
{
    __shared__ GemmSmem s;

    const int z = blockIdx.z;
    const float* X = (z == 0) ? q : (z == 1) ? k : v;
    const float* W = (z == 0) ? Wq : (z == 1) ? Wk : Wv;
    float* out = (z == 0) ? g_Q : (z == 1) ? g_K : g_V;

    const int n0 = blockIdx.x * 128;
    const int m0 = blockIdx.y * 128;
    const int tid = threadIdx.x;
    const int tx = tid & 15, ty = tid >> 4;

    float acc[8][8] = {};
    gemm_mainloop(&s, X + (size_t)m0 * DM, DM, W, n0, acc, tid);

    const int ncol = n0 + tx * 8;
    const int head = ncol >> 6;
    const int d0   = ncol & 63;
    #pragma unroll
    for (int i = 0; i < 8; ++i) {
        int m = m0 + ty * 8 + i;
        int b = m >> 11;
        int sidx = m & (SEQ - 1);
        float* dst = &out[(((size_t)(b * NH + head)) * SEQ + sidx) * HD + d0];
        *reinterpret_cast<float4*>(dst)     = make_float4(acc[i][0], acc[i][1], acc[i][2], acc[i][3]);
        *reinterpret_cast<float4*>(dst + 4) = make_float4(acc[i][4], acc[i][5], acc[i][6], acc[i][7]);
    }
}

// ----------------------------------------------------------------------------
// Stage 2: flash attention (R5-validated).  grid = (SEQ/64, B*H), 48KB smem.
// ----------------------------------------------------------------------------
__global__ void __launch_bounds__(256) flash_kernel(
    const int* __restrict__ attn_mask, const int* __restrict__ mask_future)
{
    extern __shared__ float sm[];
    float* Qt = sm;                 // [64 d][64 row]
    float* Kt = sm + 4096;          // [64 d][64 col]; reused as Ps
    float* Vs = sm + 8192;          // [64 row][64 d]
    float* Ps = Kt;

    const int tid = threadIdx.x;
    const int tx = tid & 15, ty = tid >> 4;
    const int rr = ty * 4, cc = tx * 4;
    const int qt = blockIdx.x;
    const int bh = blockIdx.y;
    const int b  = bh / NH;
    const int q0 = qt * 64;
    const bool causal = (mask_future[0] != 0);

    {
        int j = tid & 63;
        int dq = (tid >> 6) * 16;
        #pragma unroll
        for (int qd = 0; qd < 4; ++qd) {
            int d = dq + qd * 4;
            float4 qv = *reinterpret_cast<const float4*>(
                &g_Q[(((size_t)bh) * SEQ + q0 + j) * HD + d]);
            Qt[(d + 0) * 64 + j] = qv.x;
            Qt[(d + 1) * 64 + j] = qv.y;
            Qt[(d + 2) * 64 + j] = qv.z;
            Qt[(d + 3) * 64 + j] = qv.w;
        }
    }

    float m_i[4], l_i[4], o[4][4];
    #pragma unroll
    for (int i = 0; i < 4; ++i) {
        m_i[i] = -1e30f;
        l_i[i] = 0.0f;
        o[i][0] = o[i][1] = o[i][2] = o[i][3] = 0.0f;
    }

    int limit = causal ? (qt + 1) : NTILES;

    for (int kt = 0; kt < NTILES; ++kt) {
        if (kt >= limit) break;
        const int k0 = kt * 64;
        __syncthreads();

        {
            int j = tid & 63;
            int dq = (tid >> 6) * 16;
            #pragma unroll
            for (int qd = 0; qd < 4; ++qd) {
                int d = dq + qd * 4;
                float4 kv = *reinterpret_cast<const float4*>(
                    &g_K[(((size_t)bh) * SEQ + k0 + j) * HD + d]);
                Kt[(d + 0) * 64 + j] = kv.x;
                Kt[(d + 1) * 64 + j] = kv.y;
                Kt[(d + 2) * 64 + j] = kv.z;
                Kt[(d + 3) * 64 + j] = kv.w;
            }
        }
        #pragma unroll
        for (int qd = 0; qd < 4; ++qd) {
            int fi = tid + qd * 256;
            int row = fi >> 4;
            int col = (fi & 15) * 4;
            *reinterpret_cast<float4*>(&Vs[row * 64 + col]) =
                *reinterpret_cast<const float4*>(&g_V[(((size_t)bh) * SEQ + k0 + row) * HD + col]);
        }
        int mk[4];
        #pragma unroll
        for (int j = 0; j < 4; ++j)
            mk[j] = attn_mask[b * SEQ + k0 + cc + j];
        __syncthreads();

        float sacc[4][4] = {};
        #pragma unroll 16
        for (int d = 0; d < 64; ++d) {
            float4 qa = *reinterpret_cast<float4*>(&Qt[d * 64 + rr]);
            float4 kb = *reinterpret_cast<float4*>(&Kt[d * 64 + cc]);
            sacc[0][0] += qa.x * kb.x; sacc[0][1] += qa.x * kb.y; sacc[0][2] += qa.x * kb.z; sacc[0][3] += qa.x * kb.w;
            sacc[1][0] += qa.y * kb.x; sacc[1][1] += qa.y * kb.y; sacc[1][2] += qa.y * kb.z; sacc[1][3] += qa.y * kb.w;
            sacc[2][0] += qa.z * kb.x; sacc[2][1] += qa.z * kb.y; sacc[2][2] += qa.z * kb.z; sacc[2][3] += qa.z * kb.w;
            sacc[3][0] += qa.w * kb.x; sacc[3][1] += qa.w * kb.y; sacc[3][2] += qa.w * kb.z; sacc[3][3] += qa.w * kb.w;
        }
        __syncthreads();

        #pragma unroll
        for (int i = 0; i < 4; ++i) {
            int ig = q0 + rr + i;
            #pragma unroll
            for (int j = 0; j < 4; ++j) {
                int jg = k0 + cc + j;
                float sv = sacc[i][j] * SCALE;
                if (causal && jg > ig) sv += NEGV;
                if (mk[j] == 0) sv = NEGV;
                sacc[i][j] = sv;
            }
        }

        #pragma unroll
        for (int i = 0; i < 4; ++i) {
            float tm = fmaxf(fmaxf(sacc[i][0], sacc[i][1]), fmaxf(sacc[i][2], sacc[i][3]));
            #pragma unroll
            for (int off = 8; off; off >>= 1)
                tm = fmaxf(tm, __shfl_xor_sync(0xffffffffu, tm, off));
            float mnew = fmaxf(m_i[i], tm);
            float alpha = __expf(m_i[i] - mnew);
            float ps = 0.0f;
            #pragma unroll
            for (int j = 0; j < 4; ++j) {
                float p = __expf(sacc[i][j] - mnew);
                sacc[i][j] = p;
                ps += p;
            }
            #pragma unroll
            for (int off = 8; off; off >>= 1)
                ps += __shfl_xor_sync(0xffffffffu, ps, off);
            l_i[i] = l_i[i] * alpha + ps;
            m_i[i] = mnew;
            o[i][0] *= alpha; o[i][1] *= alpha; o[i][2] *= alpha; o[i][3] *= alpha;
        }

        #pragma unroll
        for (int i = 0; i < 4; ++i)
            *reinterpret_cast<float4*>(&Ps[(rr + i) * 64 + cc]) =
                make_float4(sacc[i][0], sacc[i][1], sacc[i][2], sacc[i][3]);
        __syncthreads();

        #pragma unroll 16
        for (int j = 0; j < 64; ++j) {
            float a0 = Ps[(rr + 0) * 64 + j];
            float a1 = Ps[(rr + 1) * 64 + j];
            float a2 = Ps[(rr + 2) * 64 + j];
            float a3 = Ps[(rr + 3) * 64 + j];
            float4 vv = *reinterpret_cast<float4*>(&Vs[j * 64 + cc]);
            o[0][0] += a0 * vv.x; o[0][1] += a0 * vv.y; o[0][2] += a0 * vv.z; o[0][3] += a0 * vv.w;
            o[1][0] += a1 * vv.x; o[1][1] += a1 * vv.y; o[1][2] += a1 * vv.z; o[1][3] += a1 * vv.w;
            o[2][0] += a2 * vv.x; o[2][1] += a2 * vv.y; o[2][2] += a2 * vv.z; o[2][3] += a2 * vv.w;
            o[3][0] += a3 * vv.x; o[3][1] += a3 * vv.y; o[3][2] += a3 * vv.z; o[3][3] += a3 * vv.w;
        }

        if (causal && kt == qt) {
            int lack = 0;
            #pragma unroll
            for (int i = 0; i < 4; ++i)
                if (m_i[i] <= -5000.0f) lack = 1;
            if (__syncthreads_or(lack)) limit = NTILES;
        }
    }

    #pragma unroll
    for (int i = 0; i < 4; ++i) {
        float inv = 1.0f / l_i[i];
        float4 r = make_float4(o[i][0] * inv, o[i][1] * inv, o[i][2] * inv, o[i][3] * inv);
        *reinterpret_cast<float4*>(&g_O[(((size_t)bh) * SEQ + q0 + rr + i) * HD + cc]) = r;
    }
}

// ----------------------------------------------------------------------------
// Stage 3: output projection. grid = (DM/128, MTOT/128). A gathered head-major
// via a staging pass: since g_O rows are head-major, the 16-float k-slice of
// row m crosses no head boundary per 8-chunk; cp.async directly works.
// ----------------------------------------------------------------------------
__global__ void __launch_bounds__(256) out_proj_kernel(
    const float* __restrict__ Wo, float* __restrict__ out)
{
    __shared__ GemmSmem s;

    const int n0 = blockIdx.x * 128;
    const int m0 = blockIdx.y * 128;
    const int tid = threadIdx.x;
    const int tx = tid & 15, ty = tid >> 4;

    const int am = tid >> 1;
    const int ak = (tid & 1) * 8;
    const int kb = tid >> 5;
    const int nb = (tid & 31) * 4;

    const int m = m0 + am;
    const int bb = m >> 11;
    const int ss = m & (SEQ - 1);

    float acc[8][8] = {};

    // manual mainloop (A gather differs from the contiguous-case helper)
    auto a_src = [&](int kidx) -> const float* {
        int h = kidx >> 6, dd = kidx & 63;
        return &g_O[(((size_t)(bb * NH + h)) * SEQ + ss) * HD + dd];
    };

    cp_async16(&s.As[0][am * AS_STRIDE + ak],     a_src(ak));
    cp_async16(&s.As[0][am * AS_STRIDE + ak + 4], a_src(ak + 4));
    cp_async16(&s.Bs[0][kb * 128 + nb],       &Wo[(size_t)kb * DM + n0 + nb]);
    cp_async16(&s.Bs[0][(kb + 8) * 128 + nb], &Wo[(size_t)(kb + 8) * DM + n0 + nb]);
    cp_commit();

    int buf = 0;
    for (int t = 0; t < NKT; ++t) {
        int k0n = (t + 1) * 16;
        if (t + 1 < NKT) {
            int nb2 = buf ^ 1;
            cp_async16(&s.As[nb2][am * AS_STRIDE + ak],     a_src(k0n + ak));
            cp_async16(&s.As[nb2][am * AS_STRIDE + ak + 4], a_src(k0n + ak + 4));
            cp_async16(&s.Bs[nb2][kb * 128 + nb],       &Wo[(size_t)(k0n + kb) * DM + n0 + nb]);
            cp_async16(&s.Bs[nb2][(kb + 8) * 128 + nb], &Wo[(size_t)(k0n + kb + 8) * DM + n0 + nb]);
            cp_commit();
            cp_wait<1>();
        } else {
            cp_wait<0>();
        }
        __syncthreads();

        const float* As = s.As[buf];
        const float* Bs = s.Bs[buf];
        #pragma unroll
        for (int kk = 0; kk < 16; kk += 4) {
            float4 a[8];
            #pragma unroll
            for (int i = 0; i < 8; ++i)
                a[i] = *reinterpret_cast<const float4*>(&As[(ty * 8 + i) * AS_STRIDE + kk]);
            #pragma unroll
            for (int j = 0; j < 4; ++j) {
                float4 rb0 = *reinterpret_cast<const float4*>(&Bs[(kk + j) * 128 + tx * 8]);
                float4 rb1 = *reinterpret_cast<const float4*>(&Bs[(kk + j) * 128 + tx * 8 + 4]);
                float br[8] = {rb0.x, rb0.y, rb0.z, rb0.w, rb1.x, rb1.y, rb1.z, rb1.w};
                #pragma unroll
                for (int i = 0; i < 8; ++i) {
                    float av = f4_get(a[i], j);
                    #pragma unroll
                    for (int c = 0; c < 8; ++c)
                        acc[i][c] += av * br[c];
                }
            }
        }
        buf ^= 1;
        __syncthreads();
    }

    #pragma unroll
    for (int i = 0; i < 8; ++i) {
        int mm = m0 + ty * 8 + i;
        float* dst = &out[(size_t)mm * DM + n0 + tx * 8];
        *reinterpret_cast<float4*>(dst)     = make_float4(acc[i][0], acc[i][1], acc[i][2], acc[i][3]);
        *reinterpret_cast<float4*>(dst + 4) = make_float4(acc[i][4], acc[i][5], acc[i][6], acc[i][7]);
    }
}

// ----------------------------------------------------------------------------
extern "C" void kernel_launch(void* const* d_in, const int* in_sizes, int n_in,
                              void* d_out, int out_size)
{
    const float* q    = (const float*)d_in[0];
    const float* k    = (const float*)d_in[1];
    const float* v    = (const float*)d_in[2];
    const int*   mask = (const int*)d_in[3];
    const float* Wq   = (const float*)d_in[4];
    const float* Wk   = (const float*)d_in[5];
    const float* Wv   = (const float*)d_in[6];
    const float* Wo   = (const float*)d_in[7];
    const int*   mfut = (const int*)d_in[8];
    float* out = (float*)d_out;

    const int flash_smem = 3 * 64 * 64 * (int)sizeof(float);  // 48KB (default cap)

    qkv_proj_kernel<<<dim3(DM / 128, MTOT / 128, 3), 256>>>(q, k, v, Wq, Wk, Wv);
    flash_kernel<<<dim3(SEQ / 64, BH), 256, flash_smem>>>(mask, mfut);
    out_proj_kernel<<<dim3(DM / 128, MTOT / 128), 256>>>(Wo, out);
}

// round 8
// speedup vs baseline: 1.1153x; 1.1153x over previous
#include <cuda_runtime.h>

// ----------------------------------------------------------------------------
// MultiHeadAttention, fp32.
// Stage 1/3: 128x64x16 SGEMM, 8x4 micro-tile, 256 threads (occupancy-tuned).
// Stage 2: flash attention Br=Bc=64 (R5-validated math), long-block-first
//          scheduling + vectorized P reads in GEMM2.
// ----------------------------------------------------------------------------

constexpr int BATCH = 2;
constexpr int SEQ   = 2048;
constexpr int DM    = 768;
constexpr int NH    = 12;
constexpr int HD    = 64;
constexpr int BH    = BATCH * NH;   // 24
constexpr int MTOT  = BATCH * SEQ;  // 4096
constexpr int NTILES = SEQ / 64;    // 32
constexpr float NEGV  = -10000.0f;
constexpr float SCALE = 0.125f;

__device__ float g_Q[BATCH * NH * SEQ * HD];
__device__ float g_K[BATCH * NH * SEQ * HD];
__device__ float g_V[BATCH * NH * SEQ * HD];
__device__ float g_O[BATCH * NH * SEQ * HD];

__device__ __forceinline__ float f4_get(const float4& v, int j) {
    return j == 0 ? v.x : j == 1 ? v.y : j == 2 ? v.z : v.w;
}

// ----------------------------------------------------------------------------
// Stage 1: QKV projections. 128(M)x64(N) tile, BK=16, 256 threads, 8x4/thread.
// grid = (DM/64, MTOT/128, 3). Writes head-major [B,H,S,64].
// ----------------------------------------------------------------------------
__global__ void __launch_bounds__(256) qkv_proj_kernel(
    const float* __restrict__ q, const float* __restrict__ k, const float* __restrict__ v,
    const float* __restrict__ Wq, const float* __restrict__ Wk, const float* __restrict__ Wv)
{
    __shared__ float As[16 * 128];   // As[k][m]
    __shared__ float Bs[16 * 64];    // Bs[k][n]

    const int z = blockIdx.z;
    const float* X = (z == 0) ? q : (z == 1) ? k : v;
    const float* W = (z == 0) ? Wq : (z == 1) ? Wk : Wv;
    float* out = (z == 0) ? g_Q : (z == 1) ? g_K : g_V;

    const int n0 = blockIdx.x * 64;
    const int m0 = blockIdx.y * 128;
    const int tid = threadIdx.x;
    const int tx = tid & 15, ty = tid >> 4;

    const int am = tid >> 1;            // A row 0..127
    const int ak = (tid & 1) * 8;       // A k-offset {0,8}
    const int brow = tid >> 4;          // B k-row 0..15
    const int bcol = (tid & 15) * 4;    // B col

    float acc[8][4] = {};

    for (int k0 = 0; k0 < DM; k0 += 16) {
        float4 a0 = *reinterpret_cast<const float4*>(&X[(size_t)(m0 + am) * DM + k0 + ak]);
        float4 a1 = *reinterpret_cast<const float4*>(&X[(size_t)(m0 + am) * DM + k0 + ak + 4]);
        As[(ak + 0) * 128 + am] = a0.x;
        As[(ak + 1) * 128 + am] = a0.y;
        As[(ak + 2) * 128 + am] = a0.z;
        As[(ak + 3) * 128 + am] = a0.w;
        As[(ak + 4) * 128 + am] = a1.x;
        As[(ak + 5) * 128 + am] = a1.y;
        As[(ak + 6) * 128 + am] = a1.z;
        As[(ak + 7) * 128 + am] = a1.w;
        *reinterpret_cast<float4*>(&Bs[brow * 64 + bcol]) =
            *reinterpret_cast<const float4*>(&W[(size_t)(k0 + brow) * DM + n0 + bcol]);
        __syncthreads();

        #pragma unroll
        for (int kk = 0; kk < 16; ++kk) {
            float4 ra0 = *reinterpret_cast<float4*>(&As[kk * 128 + ty * 8]);
            float4 ra1 = *reinterpret_cast<float4*>(&As[kk * 128 + ty * 8 + 4]);
            float4 b   = *reinterpret_cast<float4*>(&Bs[kk * 64 + tx * 4]);
            float ar[8] = {ra0.x, ra0.y, ra0.z, ra0.w, ra1.x, ra1.y, ra1.z, ra1.w};
            #pragma unroll
            for (int i = 0; i < 8; ++i) {
                acc[i][0] += ar[i] * b.x;
                acc[i][1] += ar[i] * b.y;
                acc[i][2] += ar[i] * b.z;
                acc[i][3] += ar[i] * b.w;
            }
        }
        __syncthreads();
    }

    const int ncol = n0 + tx * 4;
    const int head = ncol >> 6;
    const int d0   = ncol & 63;
    #pragma unroll
    for (int i = 0; i < 8; ++i) {
        int m = m0 + ty * 8 + i;
        int b = m >> 11;
        int s = m & (SEQ - 1);
        *reinterpret_cast<float4*>(&out[(((size_t)(b * NH + head)) * SEQ + s) * HD + d0]) =
            make_float4(acc[i][0], acc[i][1], acc[i][2], acc[i][3]);
    }
}

// ----------------------------------------------------------------------------
// Stage 2: flash attention.  grid = (SEQ/64, B*H), 256 threads, 48KB smem.
// Long blocks (high qt) scheduled first to balance the causal workload.
// ----------------------------------------------------------------------------
__global__ void __launch_bounds__(256) flash_kernel(
    const int* __restrict__ attn_mask, const int* __restrict__ mask_future)
{
    extern __shared__ float sm[];
    float* Qt = sm;                 // [64 d][64 row]
    float* Kt = sm + 4096;          // [64 d][64 col]; reused as Ps
    float* Vs = sm + 8192;          // [64 row][64 d]
    float* Ps = Kt;

    const int tid = threadIdx.x;
    const int tx = tid & 15, ty = tid >> 4;
    const int rr = ty * 4, cc = tx * 4;
    const int qt = (int)gridDim.x - 1 - (int)blockIdx.x;   // long blocks first
    const int bh = blockIdx.y;
    const int b  = bh / NH;
    const int q0 = qt * 64;
    const bool causal = (mask_future[0] != 0);

    // load Q tile transposed: Qt[d][row]
    {
        int j = tid & 63;
        int dq = (tid >> 6) * 16;
        #pragma unroll
        for (int qd = 0; qd < 4; ++qd) {
            int d = dq + qd * 4;
            float4 qv = *reinterpret_cast<const float4*>(
                &g_Q[(((size_t)bh) * SEQ + q0 + j) * HD + d]);
            Qt[(d + 0) * 64 + j] = qv.x;
            Qt[(d + 1) * 64 + j] = qv.y;
            Qt[(d + 2) * 64 + j] = qv.z;
            Qt[(d + 3) * 64 + j] = qv.w;
        }
    }

    float m_i[4], l_i[4], o[4][4];
    #pragma unroll
    for (int i = 0; i < 4; ++i) {
        m_i[i] = -1e30f;
        l_i[i] = 0.0f;
        o[i][0] = o[i][1] = o[i][2] = o[i][3] = 0.0f;
    }

    // Reference softmax spans ALL keys (future: raw*scale-1e4, padded: -1e4).
    // Stop at the diagonal unless some row has no valid visible key.
    int limit = causal ? (qt + 1) : NTILES;

    for (int kt = 0; kt < NTILES; ++kt) {
        if (kt >= limit) break;
        const int k0 = kt * 64;
        __syncthreads();  // prior GEMM2 reads done before overwriting Kt/Vs

        {
            int j = tid & 63;
            int dq = (tid >> 6) * 16;
            #pragma unroll
            for (int qd = 0; qd < 4; ++qd) {
                int d = dq + qd * 4;
                float4 kv = *reinterpret_cast<const float4*>(
                    &g_K[(((size_t)bh) * SEQ + k0 + j) * HD + d]);
                Kt[(d + 0) * 64 + j] = kv.x;
                Kt[(d + 1) * 64 + j] = kv.y;
                Kt[(d + 2) * 64 + j] = kv.z;
                Kt[(d + 3) * 64 + j] = kv.w;
            }
        }
        #pragma unroll
        for (int qd = 0; qd < 4; ++qd) {
            int fi = tid + qd * 256;
            int row = fi >> 4;
            int col = (fi & 15) * 4;
            *reinterpret_cast<float4*>(&Vs[row * 64 + col]) =
                *reinterpret_cast<const float4*>(&g_V[(((size_t)bh) * SEQ + k0 + row) * HD + col]);
        }
        int mk[4];
        #pragma unroll
        for (int j = 0; j < 4; ++j)
            mk[j] = attn_mask[b * SEQ + k0 + cc + j];
        __syncthreads();

        // GEMM1: S = Q K^T
        float sacc[4][4] = {};
        #pragma unroll 16
        for (int d = 0; d < 64; ++d) {
            float4 qa = *reinterpret_cast<float4*>(&Qt[d * 64 + rr]);
            float4 kb = *reinterpret_cast<float4*>(&Kt[d * 64 + cc]);
            sacc[0][0] += qa.x * kb.x; sacc[0][1] += qa.x * kb.y; sacc[0][2] += qa.x * kb.z; sacc[0][3] += qa.x * kb.w;
            sacc[1][0] += qa.y * kb.x; sacc[1][1] += qa.y * kb.y; sacc[1][2] += qa.y * kb.z; sacc[1][3] += qa.y * kb.w;
            sacc[2][0] += qa.z * kb.x; sacc[2][1] += qa.z * kb.y; sacc[2][2] += qa.z * kb.z; sacc[2][3] += qa.z * kb.w;
            sacc[3][0] += qa.w * kb.x; sacc[3][1] += qa.w * kb.y; sacc[3][2] += qa.w * kb.z; sacc[3][3] += qa.w * kb.w;
        }
        __syncthreads();  // Kt reads done before Ps (=Kt) writes

        // scale + masks (reference order)
        #pragma unroll
        for (int i = 0; i < 4; ++i) {
            int ig = q0 + rr + i;
            #pragma unroll
            for (int j = 0; j < 4; ++j) {
                int jg = k0 + cc + j;
                float sv = sacc[i][j] * SCALE;
                if (causal && jg > ig) sv += NEGV;
                if (mk[j] == 0) sv = NEGV;
                sacc[i][j] = sv;
            }
        }

        // online softmax per row
        #pragma unroll
        for (int i = 0; i < 4; ++i) {
            float tm = fmaxf(fmaxf(sacc[i][0], sacc[i][1]), fmaxf(sacc[i][2], sacc[i][3]));
            #pragma unroll
            for (int off = 8; off; off >>= 1)
                tm = fmaxf(tm, __shfl_xor_sync(0xffffffffu, tm, off));
            float mnew = fmaxf(m_i[i], tm);
            float alpha = __expf(m_i[i] - mnew);
            float ps = 0.0f;
            #pragma unroll
            for (int j = 0; j < 4; ++j) {
                float p = __expf(sacc[i][j] - mnew);
                sacc[i][j] = p;
                ps += p;
            }
            #pragma unroll
            for (int off = 8; off; off >>= 1)
                ps += __shfl_xor_sync(0xffffffffu, ps, off);
            l_i[i] = l_i[i] * alpha + ps;
            m_i[i] = mnew;
            o[i][0] *= alpha; o[i][1] *= alpha; o[i][2] *= alpha; o[i][3] *= alpha;
        }

        #pragma unroll
        for (int i = 0; i < 4; ++i)
            *reinterpret_cast<float4*>(&Ps[(rr + i) * 64 + cc]) =
                make_float4(sacc[i][0], sacc[i][1], sacc[i][2], sacc[i][3]);
        __syncthreads();

        // GEMM2: O += P V  (vectorized P row reads; same FMA order as before)
        #pragma unroll 8
        for (int j4 = 0; j4 < 64; j4 += 4) {
            float4 p0 = *reinterpret_cast<float4*>(&Ps[(rr + 0) * 64 + j4]);
            float4 p1 = *reinterpret_cast<float4*>(&Ps[(rr + 1) * 64 + j4]);
            float4 p2 = *reinterpret_cast<float4*>(&Ps[(rr + 2) * 64 + j4]);
            float4 p3 = *reinterpret_cast<float4*>(&Ps[(rr + 3) * 64 + j4]);
            #pragma unroll
            for (int jj = 0; jj < 4; ++jj) {
                float4 vv = *reinterpret_cast<float4*>(&Vs[(j4 + jj) * 64 + cc]);
                float a0 = f4_get(p0, jj);
                float a1 = f4_get(p1, jj);
                float a2 = f4_get(p2, jj);
                float a3 = f4_get(p3, jj);
                o[0][0] += a0 * vv.x; o[0][1] += a0 * vv.y; o[0][2] += a0 * vv.z; o[0][3] += a0 * vv.w;
                o[1][0] += a1 * vv.x; o[1][1] += a1 * vv.y; o[1][2] += a1 * vv.z; o[1][3] += a1 * vv.w;
                o[2][0] += a2 * vv.x; o[2][1] += a2 * vv.y; o[2][2] += a2 * vv.z; o[2][3] += a2 * vv.w;
                o[3][0] += a3 * vv.x; o[3][1] += a3 * vv.y; o[3][2] += a3 * vv.z; o[3][3] += a3 * vv.w;
            }
        }

        // all-visible-padded rows attend to future keys (reference semantics)
        if (causal && kt == qt) {
            int lack = 0;
            #pragma unroll
            for (int i = 0; i < 4; ++i)
                if (m_i[i] <= -5000.0f) lack = 1;
            if (__syncthreads_or(lack)) limit = NTILES;
        }
    }

    #pragma unroll
    for (int i = 0; i < 4; ++i) {
        float inv = 1.0f / l_i[i];
        float4 r = make_float4(o[i][0] * inv, o[i][1] * inv, o[i][2] * inv, o[i][3] * inv);
        *reinterpret_cast<float4*>(&g_O[(((size_t)bh) * SEQ + q0 + rr + i) * HD + cc]) = r;
    }
}

// ----------------------------------------------------------------------------
// Stage 3: output projection. 128x64x16 SGEMM; A gathered head-major.
// grid = (DM/64, MTOT/128).
// ----------------------------------------------------------------------------
__global__ void __launch_bounds__(256) out_proj_kernel(
    const float* __restrict__ Wo, float* __restrict__ out)
{
    __shared__ float As[16 * 128];
    __shared__ float Bs[16 * 64];

    const int n0 = blockIdx.x * 64;
    const int m0 = blockIdx.y * 128;
    const int tid = threadIdx.x;
    const int tx = tid & 15, ty = tid >> 4;

    const int am = tid >> 1;
    const int ak = (tid & 1) * 8;
    const int brow = tid >> 4;
    const int bcol = (tid & 15) * 4;

    const int m = m0 + am;
    const int bb = m >> 11;
    const int ss = m & (SEQ - 1);

    float acc[8][4] = {};

    for (int k0 = 0; k0 < DM; k0 += 16) {
        int kidx = k0 + ak;                  // 8 consecutive k within one head
        int h = kidx >> 6, dd = kidx & 63;
        const float* src = &g_O[(((size_t)(bb * NH + h)) * SEQ + ss) * HD + dd];
        float4 a0 = *reinterpret_cast<const float4*>(src);
        float4 a1 = *reinterpret_cast<const float4*>(src + 4);
        As[(ak + 0) * 128 + am] = a0.x;
        As[(ak + 1) * 128 + am] = a0.y;
        As[(ak + 2) * 128 + am] = a0.z;
        As[(ak + 3) * 128 + am] = a0.w;
        As[(ak + 4) * 128 + am] = a1.x;
        As[(ak + 5) * 128 + am] = a1.y;
        As[(ak + 6) * 128 + am] = a1.z;
        As[(ak + 7) * 128 + am] = a1.w;
        *reinterpret_cast<float4*>(&Bs[brow * 64 + bcol]) =
            *reinterpret_cast<const float4*>(&Wo[(size_t)(k0 + brow) * DM + n0 + bcol]);
        __syncthreads();

        #pragma unroll
        for (int kk = 0; kk < 16; ++kk) {
            float4 ra0 = *reinterpret_cast<float4*>(&As[kk * 128 + ty * 8]);
            float4 ra1 = *reinterpret_cast<float4*>(&As[kk * 128 + ty * 8 + 4]);
            float4 b   = *reinterpret_cast<float4*>(&Bs[kk * 64 + tx * 4]);
            float ar[8] = {ra0.x, ra0.y, ra0.z, ra0.w, ra1.x, ra1.y, ra1.z, ra1.w};
            #pragma unroll
            for (int i = 0; i < 8; ++i) {
                acc[i][0] += ar[i] * b.x;
                acc[i][1] += ar[i] * b.y;
                acc[i][2] += ar[i] * b.z;
                acc[i][3] += ar[i] * b.w;
            }
        }
        __syncthreads();
    }

    #pragma unroll
    for (int i = 0; i < 8; ++i) {
        int mm = m0 + ty * 8 + i;
        *reinterpret_cast<float4*>(&out[(size_t)mm * DM + n0 + tx * 4]) =
            make_float4(acc[i][0], acc[i][1], acc[i][2], acc[i][3]);
    }
}

// ----------------------------------------------------------------------------
extern "C" void kernel_launch(void* const* d_in, const int* in_sizes, int n_in,
                              void* d_out, int out_size)
{
    const float* q    = (const float*)d_in[0];
    const float* k    = (const float*)d_in[1];
    const float* v    = (const float*)d_in[2];
    const int*   mask = (const int*)d_in[3];
    const float* Wq   = (const float*)d_in[4];
    const float* Wk   = (const float*)d_in[5];
    const float* Wv   = (const float*)d_in[6];
    const float* Wo   = (const float*)d_in[7];
    const int*   mfut = (const int*)d_in[8];
    float* out = (float*)d_out;

    const int flash_smem = 3 * 64 * 64 * (int)sizeof(float);  // 48KB

    qkv_proj_kernel<<<dim3(DM / 64, MTOT / 128, 3), 256>>>(q, k, v, Wq, Wk, Wv);
    flash_kernel<<<dim3(SEQ / 64, BH), 256, flash_smem>>>(mask, mfut);
    out_proj_kernel<<<dim3(DM / 64, MTOT / 128), 256>>>(Wo, out);
}